// round 9
// baseline (speedup 1.0000x reference)
#include <cuda_runtime.h>
#include <math.h>

#define NN 100000
#define EE 1600000
#define INC 32
#define HC  64
#define LC  16
#define GG  64
#define NB1 98          // ceil(NN/1024) scan blocks

typedef unsigned long long u64;

// ---- packed f32x2 helpers (sm_103a FFMA2/FADD2 via PTX) ----
__device__ __forceinline__ u64 fadd2(u64 a, u64 b) {
    u64 d; asm("add.rn.f32x2 %0,%1,%2;" : "=l"(d) : "l"(a), "l"(b)); return d;
}
__device__ __forceinline__ u64 fmul2(u64 a, u64 b) {
    u64 d; asm("mul.rn.f32x2 %0,%1,%2;" : "=l"(d) : "l"(a), "l"(b)); return d;
}
__device__ __forceinline__ u64 ffma2(u64 a, u64 b, u64 c) {
    u64 d; asm("fma.rn.f32x2 %0,%1,%2,%3;" : "=l"(d) : "l"(a), "l"(b), "l"(c)); return d;
}
__device__ __forceinline__ u64 pack2(float x, float y) {
    u64 d; asm("mov.b64 %0,{%1,%2};" : "=l"(d) : "f"(x), "f"(y)); return d;
}

// ---- device scratch (static, no allocation) ----
__device__ int   g_degi[NN];
__device__ int   g_part[NN];
__device__ int   g_off[NN];
__device__ int   g_cur[NN];
__device__ int   g_csr[EE];
__device__ int   g_bsum[128];
__device__ float g_dinv[NN];
__device__ float g_xws[NN * HC];    // P = (in@W)*dinv payload
__device__ float g_buf0[NN * HC];
__device__ float g_buf1[NN * HC];
__device__ float g_sums[GG * HC];
__device__ float g_cnt[GG];
__device__ float g_XW[GG * HC];     // (relu(z@Wdp+b)) @ W_dec0, per graph

// ------------------------------------------------------------------
__global__ void k_init() {
    int i = blockIdx.x * blockDim.x + threadIdx.x;
    if (i < NN) g_degi[i] = 0;
    if (i < GG * HC) g_sums[i] = 0.f;
    if (i < GG) g_cnt[i] = 0.f;
}

__global__ void k_count(const int* __restrict__ ei) {
    int e = blockIdx.x * blockDim.x + threadIdx.x;
    if (e < EE) atomicAdd(&g_degi[ei[EE + e]], 1);
}

// block-level exclusive scan of degi (1024/block)
__global__ void __launch_bounds__(1024) k_scan1() {
    __shared__ int sm[1024];
    const int tid = threadIdx.x;
    const int i = blockIdx.x * 1024 + tid;
    const int v = (i < NN) ? g_degi[i] : 0;
    sm[tid] = v;
    __syncthreads();
    for (int o = 1; o < 1024; o <<= 1) {
        int t = (tid >= o) ? sm[tid - o] : 0;
        __syncthreads();
        sm[tid] += t;
        __syncthreads();
    }
    if (i < NN) g_part[i] = sm[tid] - v;          // exclusive
    if (tid == 1023) g_bsum[blockIdx.x] = sm[1023];
}

// scan of block sums (redundant per block, in smem) + finalize offsets/dinv
__global__ void __launch_bounds__(1024) k_scan3() {
    __shared__ int sb[128];
    __shared__ int sv[128];
    const int tid = threadIdx.x;
    if (tid < 128) {
        int v = (tid < NB1) ? g_bsum[tid] : 0;
        sb[tid] = v; sv[tid] = v;
    }
    __syncthreads();
    for (int o = 1; o < 128; o <<= 1) {
        int t = 0;
        if (tid >= o && tid < 128) t = sb[tid - o];
        __syncthreads();
        if (tid < 128) sb[tid] += t;
        __syncthreads();
    }
    const int i = blockIdx.x * 1024 + tid;
    if (i >= NN) return;
    const int base = sb[blockIdx.x] - sv[blockIdx.x];   // exclusive block base
    const int o = g_part[i] + base;
    g_off[i] = o;
    g_cur[i] = o;
    g_dinv[i] = rsqrtf((float)g_degi[i] + 1.0f);
}

__global__ void k_fill(const int* __restrict__ ei) {
    int e = blockIdx.x * blockDim.x + threadIdx.x;
    if (e >= EE) return;
    const int src = __ldg(&ei[e]);
    const int dst = __ldg(&ei[EE + e]);
    const int pos = atomicAdd(&g_cur[dst], 1);
    g_csr[pos] = src;
}

// ------------------------------------------------------------------
// conv0 fused gather (quarter-warp/node, packed math):
// out[n] = dinv[n] * ( sum_s x[s]*dinv[s]  +  x[n]*dinv[n] )
// ------------------------------------------------------------------
__global__ void __launch_bounds__(256)
k_gather32x(const float* __restrict__ x, float* __restrict__ out) {
    const int wid = threadIdx.x >> 5;
    const int lane = threadIdx.x & 31;
    const int q = lane >> 3;
    const int l8 = lane & 7;
    const int n = blockIdx.x * 32 + wid * 4 + q;
    if (n >= NN) return;
    const int o = __ldg(&g_off[n]);
    const int d = __ldg(&g_degi[n]);
    const float dn = __ldg(&g_dinv[n]);

    u64 acc0 = 0, acc1 = 0;
    int i = 0;
    for (; i + 4 <= d; i += 4) {
        const int s0 = __ldg(&g_csr[o + i]);
        const int s1 = __ldg(&g_csr[o + i + 1]);
        const int s2 = __ldg(&g_csr[o + i + 2]);
        const int s3 = __ldg(&g_csr[o + i + 3]);
        const u64 c0 = pack2(__ldg(&g_dinv[s0]), __ldg(&g_dinv[s0]));
        const u64 c1 = pack2(__ldg(&g_dinv[s1]), __ldg(&g_dinv[s1]));
        const u64 c2 = pack2(__ldg(&g_dinv[s2]), __ldg(&g_dinv[s2]));
        const u64 c3 = pack2(__ldg(&g_dinv[s3]), __ldg(&g_dinv[s3]));
        const ulonglong2 u0 = *(const ulonglong2*)(x + (long)s0 * INC + l8 * 4);
        const ulonglong2 u1 = *(const ulonglong2*)(x + (long)s1 * INC + l8 * 4);
        const ulonglong2 u2 = *(const ulonglong2*)(x + (long)s2 * INC + l8 * 4);
        const ulonglong2 u3 = *(const ulonglong2*)(x + (long)s3 * INC + l8 * 4);
        acc0 = ffma2(u0.x, c0, ffma2(u1.x, c1, ffma2(u2.x, c2, ffma2(u3.x, c3, acc0))));
        acc1 = ffma2(u0.y, c0, ffma2(u1.y, c1, ffma2(u2.y, c2, ffma2(u3.y, c3, acc1))));
    }
    for (; i < d; i++) {
        const int s = __ldg(&g_csr[o + i]);
        const float ds = __ldg(&g_dinv[s]);
        const u64 cp = pack2(ds, ds);
        const ulonglong2 u = *(const ulonglong2*)(x + (long)s * INC + l8 * 4);
        acc0 = ffma2(u.x, cp, acc0);
        acc1 = ffma2(u.y, cp, acc1);
    }
    const u64 dn2 = pack2(dn, dn);
    const ulonglong2 xu = *(const ulonglong2*)(x + (long)n * INC + l8 * 4);
    ulonglong2 r;
    r.x = fmul2(ffma2(xu.x, dn2, acc0), dn2);
    r.y = fmul2(ffma2(xu.y, dn2, acc1), dn2);
    *(ulonglong2*)(out + (long)n * INC + l8 * 4) = r;
}

// ------------------------------------------------------------------
// 64-ch fp32 gather (quarter-warp/node, 8 floats/lane, packed adds):
// out = dinv[n]*(sum P[s] + P[n]) + b
// ------------------------------------------------------------------
__global__ void __launch_bounds__(256)
k_gather64(const float* __restrict__ P, const float* __restrict__ b,
           float* __restrict__ out) {
    const int wid = threadIdx.x >> 5;
    const int lane = threadIdx.x & 31;
    const int q = lane >> 3;
    const int l8 = lane & 7;
    const int n = blockIdx.x * 32 + wid * 4 + q;
    if (n >= NN) return;
    const int o = __ldg(&g_off[n]);
    const int d = __ldg(&g_degi[n]);

    const float* rowp = P + (long)n * HC + l8 * 8;
    ulonglong2 aA = *(const ulonglong2*)(rowp);
    ulonglong2 aB = *(const ulonglong2*)(rowp + 4);
    u64 acc0 = aA.x, acc1 = aA.y, acc2 = aB.x, acc3 = aB.y;

    int i = 0;
    for (; i + 4 <= d; i += 4) {
        const int s0 = __ldg(&g_csr[o + i]);
        const int s1 = __ldg(&g_csr[o + i + 1]);
        const int s2 = __ldg(&g_csr[o + i + 2]);
        const int s3 = __ldg(&g_csr[o + i + 3]);
        const float* p0 = P + (long)s0 * HC + l8 * 8;
        const float* p1 = P + (long)s1 * HC + l8 * 8;
        const float* p2 = P + (long)s2 * HC + l8 * 8;
        const float* p3 = P + (long)s3 * HC + l8 * 8;
        const ulonglong2 a0 = *(const ulonglong2*)(p0);
        const ulonglong2 b0 = *(const ulonglong2*)(p0 + 4);
        const ulonglong2 a1 = *(const ulonglong2*)(p1);
        const ulonglong2 b1 = *(const ulonglong2*)(p1 + 4);
        const ulonglong2 a2 = *(const ulonglong2*)(p2);
        const ulonglong2 b2 = *(const ulonglong2*)(p2 + 4);
        const ulonglong2 a3 = *(const ulonglong2*)(p3);
        const ulonglong2 b3 = *(const ulonglong2*)(p3 + 4);
        acc0 = fadd2(fadd2(fadd2(a0.x, a1.x), fadd2(a2.x, a3.x)), acc0);
        acc1 = fadd2(fadd2(fadd2(a0.y, a1.y), fadd2(a2.y, a3.y)), acc1);
        acc2 = fadd2(fadd2(fadd2(b0.x, b1.x), fadd2(b2.x, b3.x)), acc2);
        acc3 = fadd2(fadd2(fadd2(b0.y, b1.y), fadd2(b2.y, b3.y)), acc3);
    }
    for (; i < d; i++) {
        const int s = __ldg(&g_csr[o + i]);
        const float* p = P + (long)s * HC + l8 * 8;
        const ulonglong2 a = *(const ulonglong2*)(p);
        const ulonglong2 bb = *(const ulonglong2*)(p + 4);
        acc0 = fadd2(acc0, a.x); acc1 = fadd2(acc1, a.y);
        acc2 = fadd2(acc2, bb.x); acc3 = fadd2(acc3, bb.y);
    }
    const float dn = __ldg(&g_dinv[n]);
    const u64 dn2 = pack2(dn, dn);
    const ulonglong2 bA = *(const ulonglong2*)(b + l8 * 8);
    const ulonglong2 bB = *(const ulonglong2*)(b + l8 * 8 + 4);
    ulonglong2 rA, rB;
    rA.x = ffma2(acc0, dn2, bA.x); rA.y = ffma2(acc1, dn2, bA.y);
    rB.x = ffma2(acc2, dn2, bB.x); rB.y = ffma2(acc3, dn2, bB.y);
    float* op = out + (long)n * HC + l8 * 8;
    *(ulonglong2*)(op) = rA;
    *(ulonglong2*)(op + 4) = rB;
}

// dec0 gather via graph table (half-warp/node, smem table, packed math)
__global__ void __launch_bounds__(256)
k_gather_tab(const int* __restrict__ batch, const float* __restrict__ b,
             float* __restrict__ out) {
    __shared__ __align__(16) float XWs[GG * HC];      // 16KB
    const int tid = threadIdx.x;
    {
        const float4* s4 = (const float4*)g_XW;
        float4* d4 = (float4*)XWs;
        for (int i = tid; i < GG * HC / 4; i += 256) d4[i] = s4[i];
    }
    __syncthreads();

    const int wid = tid >> 5;
    const int lane = tid & 31;
    const int h = lane >> 4;
    const int l16 = lane & 15;
    const int n = blockIdx.x * 16 + wid * 2 + h;
    if (n >= NN) return;
    const int o = __ldg(&g_off[n]);
    const int d = __ldg(&g_degi[n]);
    const float dn = __ldg(&g_dinv[n]);

    const int gn = __ldg(&batch[n]);
    const u64 dn2 = pack2(dn, dn);
    ulonglong2 sv = *(const ulonglong2*)(XWs + gn * HC + l16 * 4);
    u64 acc0 = fmul2(sv.x, dn2);
    u64 acc1 = fmul2(sv.y, dn2);

    int i = 0;
    for (; i + 4 <= d; i += 4) {
        const int s0 = __ldg(&g_csr[o + i]);
        const int s1 = __ldg(&g_csr[o + i + 1]);
        const int s2 = __ldg(&g_csr[o + i + 2]);
        const int s3 = __ldg(&g_csr[o + i + 3]);
        const int ga = __ldg(&batch[s0]);
        const int gb = __ldg(&batch[s1]);
        const int gc = __ldg(&batch[s2]);
        const int gd = __ldg(&batch[s3]);
        const u64 c0 = pack2(__ldg(&g_dinv[s0]), __ldg(&g_dinv[s0]));
        const u64 c1 = pack2(__ldg(&g_dinv[s1]), __ldg(&g_dinv[s1]));
        const u64 c2 = pack2(__ldg(&g_dinv[s2]), __ldg(&g_dinv[s2]));
        const u64 c3 = pack2(__ldg(&g_dinv[s3]), __ldg(&g_dinv[s3]));
        const ulonglong2 v0 = *(const ulonglong2*)(XWs + ga * HC + l16 * 4);
        const ulonglong2 v1 = *(const ulonglong2*)(XWs + gb * HC + l16 * 4);
        const ulonglong2 v2 = *(const ulonglong2*)(XWs + gc * HC + l16 * 4);
        const ulonglong2 v3 = *(const ulonglong2*)(XWs + gd * HC + l16 * 4);
        acc0 = ffma2(v0.x, c0, ffma2(v1.x, c1, ffma2(v2.x, c2, ffma2(v3.x, c3, acc0))));
        acc1 = ffma2(v0.y, c0, ffma2(v1.y, c1, ffma2(v2.y, c2, ffma2(v3.y, c3, acc1))));
    }
    for (; i < d; i++) {
        const int s = __ldg(&g_csr[o + i]);
        const int g = __ldg(&batch[s]);
        const float ds = __ldg(&g_dinv[s]);
        const u64 cp = pack2(ds, ds);
        const ulonglong2 v = *(const ulonglong2*)(XWs + g * HC + l16 * 4);
        acc0 = ffma2(v.x, cp, acc0);
        acc1 = ffma2(v.y, cp, acc1);
    }
    const ulonglong2 b2v = *(const ulonglong2*)(b + l16 * 4);
    ulonglong2 r;
    r.x = ffma2(acc0, dn2, b2v.x);
    r.y = ffma2(acc1, dn2, b2v.y);
    *(ulonglong2*)(out + (long)n * HC + l16 * 4) = r;
}

// 32-ch fp32 payload gather (quarter-warp/node, packed adds)
__global__ void __launch_bounds__(256)
k_gather32p(const float* __restrict__ P, const float* __restrict__ b,
            float* __restrict__ out) {
    const int wid = threadIdx.x >> 5;
    const int lane = threadIdx.x & 31;
    const int q = lane >> 3;
    const int l8 = lane & 7;
    const int n = blockIdx.x * 32 + wid * 4 + q;
    if (n >= NN) return;
    const int o = __ldg(&g_off[n]);
    const int d = __ldg(&g_degi[n]);

    ulonglong2 a = *(const ulonglong2*)(P + (long)n * INC + l8 * 4);
    u64 acc0 = a.x, acc1 = a.y;
    int i = 0;
    for (; i + 4 <= d; i += 4) {
        const int s0 = __ldg(&g_csr[o + i]);
        const int s1 = __ldg(&g_csr[o + i + 1]);
        const int s2 = __ldg(&g_csr[o + i + 2]);
        const int s3 = __ldg(&g_csr[o + i + 3]);
        const ulonglong2 u0 = *(const ulonglong2*)(P + (long)s0 * INC + l8 * 4);
        const ulonglong2 u1 = *(const ulonglong2*)(P + (long)s1 * INC + l8 * 4);
        const ulonglong2 u2 = *(const ulonglong2*)(P + (long)s2 * INC + l8 * 4);
        const ulonglong2 u3 = *(const ulonglong2*)(P + (long)s3 * INC + l8 * 4);
        acc0 = fadd2(fadd2(fadd2(u0.x, u1.x), fadd2(u2.x, u3.x)), acc0);
        acc1 = fadd2(fadd2(fadd2(u0.y, u1.y), fadd2(u2.y, u3.y)), acc1);
    }
    for (; i < d; i++) {
        const int s = __ldg(&g_csr[o + i]);
        const ulonglong2 u = *(const ulonglong2*)(P + (long)s * INC + l8 * 4);
        acc0 = fadd2(acc0, u.x);
        acc1 = fadd2(acc1, u.y);
    }
    const float dn = __ldg(&g_dinv[n]);
    const u64 dn2 = pack2(dn, dn);
    const ulonglong2 b2v = *(const ulonglong2*)(b + l8 * 4);
    ulonglong2 r;
    r.x = ffma2(acc0, dn2, b2v.x);
    r.y = ffma2(acc1, dn2, b2v.y);
    *(ulonglong2*)(out + (long)n * INC + l8 * 4) = r;
}

// ------------------------------------------------------------------
// GEMM with packed f32x2 FMA: 4 nodes x 8 channels per thread.
// MODE 0: out = in@W + b          MODE 1: payload = (in@W)*dinv
// ------------------------------------------------------------------
template <int KIN, int COUT, bool RELUIN, int MODE>
__global__ void __launch_bounds__(256, 3)
k_gemm(const float* __restrict__ in,
       const float* __restrict__ W,
       const float* __restrict__ b,
       float* __restrict__ dst) {
    constexpr int TPN = COUT / 8;
    constexpr int NG  = 256 / TPN;
    constexpr int NPB = NG * 4;
    constexpr int XSS = KIN + 1;

    __shared__ __align__(16) float Ws[KIN * COUT];
    __shared__ __align__(16) float bs[COUT];
    __shared__ float xs[NPB * XSS];

    const int tid = threadIdx.x;
    const int n0 = blockIdx.x * NPB;

    {
        const float4* W4 = (const float4*)W;
        float4* Ws4 = (float4*)Ws;
#pragma unroll
        for (int i = tid; i < KIN * COUT / 4; i += 256) Ws4[i] = W4[i];
    }
    if (tid < COUT) bs[tid] = (MODE == 0) ? b[tid] : 0.f;

    {
        constexpr int QPR = KIN / 4;
        constexpr int NQ = NPB * QPR;
        for (int i = tid; i < NQ; i += 256) {
            const int row = i / QPR;
            const int qc = i % QPR;
            float4 v = make_float4(0.f, 0.f, 0.f, 0.f);
            if (n0 + row < NN) {
                v = *(const float4*)(in + (long)(n0 + row) * KIN + qc * 4);
                if (RELUIN) {
                    v.x = fmaxf(v.x, 0.f); v.y = fmaxf(v.y, 0.f);
                    v.z = fmaxf(v.z, 0.f); v.w = fmaxf(v.w, 0.f);
                }
            }
            float* p = xs + row * XSS + qc * 4;
            p[0] = v.x; p[1] = v.y; p[2] = v.z; p[3] = v.w;
        }
    }
    __syncthreads();

    const int tc = tid % TPN;
    const int ng = tid / TPN;
    const int c0 = tc * 8;
    const int nb = ng * 4;

    u64 acc[4][4];
#pragma unroll
    for (int j = 0; j < 4; j++)
#pragma unroll
        for (int m = 0; m < 4; m++) acc[j][m] = 0ULL;

#pragma unroll 8
    for (int k = 0; k < KIN; k++) {
        const ulonglong2 wA = *(const ulonglong2*)(Ws + k * COUT + c0);
        const ulonglong2 wB = *(const ulonglong2*)(Ws + k * COUT + c0 + 4);
        u64 xp[4];
#pragma unroll
        for (int j = 0; j < 4; j++) {
            const float xv = xs[(nb + j) * XSS + k];
            xp[j] = pack2(xv, xv);
        }
#pragma unroll
        for (int j = 0; j < 4; j++) {
            acc[j][0] = ffma2(xp[j], wA.x, acc[j][0]);
            acc[j][1] = ffma2(xp[j], wA.y, acc[j][1]);
            acc[j][2] = ffma2(xp[j], wB.x, acc[j][2]);
            acc[j][3] = ffma2(xp[j], wB.y, acc[j][3]);
        }
    }

#pragma unroll
    for (int j = 0; j < 4; j++) {
        const int n = n0 + nb + j;
        if (n >= NN) break;
        ulonglong2 oA, oB;
        if (MODE == 1) {
            const float dd = g_dinv[n];
            const u64 d2 = pack2(dd, dd);
            oA.x = fmul2(acc[j][0], d2); oA.y = fmul2(acc[j][1], d2);
            oB.x = fmul2(acc[j][2], d2); oB.y = fmul2(acc[j][3], d2);
        } else {
            const ulonglong2 bA = *(const ulonglong2*)(bs + c0);
            const ulonglong2 bB = *(const ulonglong2*)(bs + c0 + 4);
            oA.x = fadd2(acc[j][0], bA.x); oA.y = fadd2(acc[j][1], bA.y);
            oB.x = fadd2(acc[j][2], bB.x); oB.y = fadd2(acc[j][3], bB.y);
        }
        float* op = dst + (long)n * COUT + c0;
        *(ulonglong2*)(op) = oA;
        *(ulonglong2*)(op + 4) = oB;
    }
}

// ------------------------------------------------------------------
// Pool: register run-length accumulation over sorted batch ids.
// ------------------------------------------------------------------
__global__ void k_pool(const int* __restrict__ batch, const float* __restrict__ h) {
    const int tid = threadIdx.x;
    const int c = tid % HC;
    const int r = tid / HC;
    float acc = 0.f;
    float cacc = 0.f;
    int curg = -1;
    for (int n = blockIdx.x * 4 + r; n < NN; n += gridDim.x * 4) {
        const int g = __ldg(&batch[n]);
        if (g != curg) {
            if (curg >= 0) {
                atomicAdd(&g_sums[curg * HC + c], acc);
                if (c == 0) atomicAdd(&g_cnt[curg], cacc);
            }
            acc = 0.f; cacc = 0.f; curg = g;
        }
        acc += fmaxf(h[(long)n * HC + c], 0.f);
        cacc += 1.f;
    }
    if (curg >= 0) {
        atomicAdd(&g_sums[curg * HC + c], acc);
        if (c == 0) atomicAdd(&g_cnt[curg], cacc);
    }
}

// ------------------------------------------------------------------
// Fused latent path: z = (sums/cnt)@Wp + bp  (also to d_out);
// D = relu(z@Wdp + bdp); XW = D @ W_dec0.   One block of 1024.
// ------------------------------------------------------------------
__global__ void __launch_bounds__(1024)
k_latent(const float* __restrict__ Wp, const float* __restrict__ bp,
         const float* __restrict__ Wdp, const float* __restrict__ bdp,
         const float* __restrict__ Wd0, float* __restrict__ zout) {
    __shared__ float zs[GG * LC];
    __shared__ float Ds[GG * HC];
    __shared__ float Wd0s[HC * HC];
    const int tid = threadIdx.x;        // 0..1023 = GG*LC exactly

    {
        const int g = tid / LC, l = tid % LC;
        const float inv = 1.0f / fmaxf(g_cnt[g], 1.0f);
        float s = bp[l];
#pragma unroll
        for (int k = 0; k < HC; k++)
            s = fmaf(g_sums[g * HC + k] * inv, Wp[k * LC + l], s);
        zs[g * LC + l] = s;
        zout[g * LC + l] = s;
    }
    for (int i = tid; i < HC * HC; i += 1024) Wd0s[i] = Wd0[i];
    __syncthreads();

    for (int i = tid; i < GG * HC; i += 1024) {
        const int g = i / HC, c = i % HC;
        float s = bdp[c];
#pragma unroll
        for (int k = 0; k < LC; k++) s = fmaf(zs[g * LC + k], Wdp[k * HC + c], s);
        Ds[i] = fmaxf(s, 0.f);
    }
    __syncthreads();

    for (int i = tid; i < GG * HC; i += 1024) {
        const int g = i / HC, c = i % HC;
        float s = 0.f;
#pragma unroll 16
        for (int k = 0; k < HC; k++) s = fmaf(Ds[g * HC + k], Wd0s[k * HC + c], s);
        g_XW[i] = s;
    }
}

// ------------------------------------------------------------------
extern "C" void kernel_launch(void* const* d_in, const int* in_sizes, int n_in,
                              void* d_out, int out_size) {
    const float* x       = (const float*)d_in[0];
    const int*   ei      = (const int*)  d_in[1];
    const int*   batch   = (const int*)  d_in[2];
    const float* W_enc0  = (const float*)d_in[3];
    const float* b_enc0  = (const float*)d_in[4];
    const float* W_enc1  = (const float*)d_in[5];
    const float* b_enc1  = (const float*)d_in[6];
    const float* W_enc2  = (const float*)d_in[7];
    const float* b_enc2  = (const float*)d_in[8];
    const float* W_proj  = (const float*)d_in[9];
    const float* b_proj  = (const float*)d_in[10];
    const float* W_decp  = (const float*)d_in[11];
    const float* b_decp  = (const float*)d_in[12];
    const float* W_dec0  = (const float*)d_in[13];
    const float* b_dec0  = (const float*)d_in[14];
    const float* W_dec1  = (const float*)d_in[15];
    const float* b_dec1  = (const float*)d_in[16];

    float* out  = (float*)d_out;
    float* xrec = out;             // [NN, INC]
    float* zout = out + NN * INC;  // [GG, LC]

    float *p_xws, *p_buf0, *p_buf1;
    cudaGetSymbolAddress((void**)&p_xws,  g_xws);
    cudaGetSymbolAddress((void**)&p_buf0, g_buf0);
    cudaGetSymbolAddress((void**)&p_buf1, g_buf1);

    const int TB = 256;
    const int gN    = (NN + TB - 1) / TB;
    const int gE    = (EE + TB - 1) / TB;
    const int gA64  = (NN + 127) / 128;     // GEMM COUT=64
    const int gA32  = (NN + 255) / 256;     // GEMM COUT=32
    const int gG64  = (NN + 15) / 16;       // gather_tab: 16 nodes/block
    const int gG32  = (NN + 31) / 32;       // quarter-warp gathers: 32 nodes/block

    // ---- degree, CSR build, dinv ----
    k_init<<<gN, TB>>>();
    k_count<<<gE, TB>>>(ei);
    k_scan1<<<NB1, 1024>>>();
    k_scan3<<<NB1, 1024>>>();
    k_fill<<<gE, TB>>>(ei);

    // ---- conv0 (fused aggregate in input space, then GEMM) ----
    k_gather32x<<<gG32, TB>>>(x, p_buf1);
    k_gemm<INC, HC, false, 0><<<gA64, TB>>>(p_buf1, W_enc0, b_enc0, p_buf0);

    // ---- conv1 ----
    k_gemm<HC, HC, true, 1><<<gA64, TB>>>(p_buf0, W_enc1, nullptr, p_xws);
    k_gather64<<<gG32, TB>>>(p_xws, b_enc1, p_buf1);
    // ---- conv2 ----
    k_gemm<HC, HC, true, 1><<<gA64, TB>>>(p_buf1, W_enc2, nullptr, p_xws);
    k_gather64<<<gG32, TB>>>(p_xws, b_enc2, p_buf0);

    // ---- pool + fused latent/decoder head ----
    k_pool<<<592, TB>>>(batch, p_buf0);
    k_latent<<<1, 1024>>>(W_proj, b_proj, W_decp, b_decp, W_dec0, zout);

    // ---- dec conv0 via graph table (gather, no N-wide GEMM) ----
    k_gather_tab<<<gG64, TB>>>(batch, b_dec0, p_buf1);

    // ---- dec conv1 ----
    k_gemm<HC, INC, true, 1><<<gA32, TB>>>(p_buf1, W_dec1, nullptr, p_xws);
    k_gather32p<<<gG32, TB>>>(p_xws, b_dec1, xrec);
}

// round 10
// speedup vs baseline: 1.1160x; 1.1160x over previous
#include <cuda_runtime.h>
#include <cuda_fp16.h>
#include <math.h>

#define NN 100000
#define EE 1600000
#define INC 32
#define HC  64
#define LC  16
#define GG  64
#define NB1 98          // ceil(NN/1024) scan blocks

// ---- device scratch (static, no allocation) ----
__device__ int   g_degi[NN];
__device__ int   g_part[NN];
__device__ int   g_off[NN];
__device__ int   g_cur[NN];
__device__ int   g_csr[EE];
__device__ int   g_bsum[128];
__device__ float g_dinv[NN];
__device__ float g_xws[NN * HC];    // payload: fp32 rows OR packed half rows
__device__ float g_buf0[NN * HC];
__device__ float g_buf1[NN * HC];
__device__ float g_sums[GG * HC];
__device__ float g_cnt[GG];
__device__ float g_XW[GG * HC];     // (relu(z@Wdp+b)) @ W_dec0, per graph

// ------------------------------------------------------------------
__global__ void k_init() {
    int i = blockIdx.x * blockDim.x + threadIdx.x;
    if (i < NN) g_degi[i] = 0;
    if (i < GG * HC) g_sums[i] = 0.f;
    if (i < GG) g_cnt[i] = 0.f;
}

__global__ void k_count(const int* __restrict__ ei) {
    int e = blockIdx.x * blockDim.x + threadIdx.x;
    if (e < EE) atomicAdd(&g_degi[ei[EE + e]], 1);
}

// block-level exclusive scan of degi (1024/block)
__global__ void __launch_bounds__(1024) k_scan1() {
    __shared__ int sm[1024];
    const int tid = threadIdx.x;
    const int i = blockIdx.x * 1024 + tid;
    const int v = (i < NN) ? g_degi[i] : 0;
    sm[tid] = v;
    __syncthreads();
    for (int o = 1; o < 1024; o <<= 1) {
        int t = (tid >= o) ? sm[tid - o] : 0;
        __syncthreads();
        sm[tid] += t;
        __syncthreads();
    }
    if (i < NN) g_part[i] = sm[tid] - v;          // exclusive
    if (tid == 1023) g_bsum[blockIdx.x] = sm[1023];
}

// scan of block sums (redundant per block, in smem) + finalize offsets/dinv
__global__ void __launch_bounds__(1024) k_scan3() {
    __shared__ int sb[128];
    __shared__ int sv[128];
    const int tid = threadIdx.x;
    if (tid < 128) {
        int v = (tid < NB1) ? g_bsum[tid] : 0;
        sb[tid] = v; sv[tid] = v;
    }
    __syncthreads();
    for (int o = 1; o < 128; o <<= 1) {
        int t = 0;
        if (tid >= o && tid < 128) t = sb[tid - o];
        __syncthreads();
        if (tid < 128) sb[tid] += t;
        __syncthreads();
    }
    const int i = blockIdx.x * 1024 + tid;
    if (i >= NN) return;
    const int base = sb[blockIdx.x] - sv[blockIdx.x];   // exclusive block base
    const int o = g_part[i] + base;
    g_off[i] = o;
    g_cur[i] = o;
    g_dinv[i] = rsqrtf((float)g_degi[i] + 1.0f);
}

__global__ void k_fill(const int* __restrict__ ei) {
    int e = blockIdx.x * blockDim.x + threadIdx.x;
    if (e >= EE) return;
    const int src = __ldg(&ei[e]);
    const int dst = __ldg(&ei[EE + e]);
    const int pos = atomicAdd(&g_cur[dst], 1);
    g_csr[pos] = src;
}

// ------------------------------------------------------------------
// conv0 fused gather (quarter-warp/node, float4 row, unroll 8):
// out[n] = dinv[n] * ( sum_s x[s]*dinv[s]  +  x[n]*dinv[n] )
// ------------------------------------------------------------------
__global__ void __launch_bounds__(256)
k_gather32x(const float* __restrict__ x, float* __restrict__ out) {
    const int wid = threadIdx.x >> 5;
    const int lane = threadIdx.x & 31;
    const int q = lane >> 3;
    const int l8 = lane & 7;
    const int n = blockIdx.x * 32 + wid * 4 + q;
    if (n >= NN) return;
    const int o = __ldg(&g_off[n]);
    const int d = __ldg(&g_degi[n]);
    const float dn = __ldg(&g_dinv[n]);

    float4 acc = make_float4(0.f, 0.f, 0.f, 0.f);
    int i = 0;
    for (; i + 8 <= d; i += 8) {
        int s[8]; float ds[8]; float4 v[8];
#pragma unroll
        for (int m = 0; m < 8; m++) s[m] = __ldg(&g_csr[o + i + m]);
#pragma unroll
        for (int m = 0; m < 8; m++) ds[m] = __ldg(&g_dinv[s[m]]);
#pragma unroll
        for (int m = 0; m < 8; m++) v[m] = *(const float4*)(x + (long)s[m] * INC + l8 * 4);
#pragma unroll
        for (int m = 0; m < 8; m++) {
            acc.x = fmaf(v[m].x, ds[m], acc.x);
            acc.y = fmaf(v[m].y, ds[m], acc.y);
            acc.z = fmaf(v[m].z, ds[m], acc.z);
            acc.w = fmaf(v[m].w, ds[m], acc.w);
        }
    }
    for (; i + 4 <= d; i += 4) {
        int s[4]; float ds[4]; float4 v[4];
#pragma unroll
        for (int m = 0; m < 4; m++) s[m] = __ldg(&g_csr[o + i + m]);
#pragma unroll
        for (int m = 0; m < 4; m++) ds[m] = __ldg(&g_dinv[s[m]]);
#pragma unroll
        for (int m = 0; m < 4; m++) v[m] = *(const float4*)(x + (long)s[m] * INC + l8 * 4);
#pragma unroll
        for (int m = 0; m < 4; m++) {
            acc.x = fmaf(v[m].x, ds[m], acc.x);
            acc.y = fmaf(v[m].y, ds[m], acc.y);
            acc.z = fmaf(v[m].z, ds[m], acc.z);
            acc.w = fmaf(v[m].w, ds[m], acc.w);
        }
    }
    for (; i < d; i++) {
        const int s = __ldg(&g_csr[o + i]);
        const float ds = __ldg(&g_dinv[s]);
        const float4 v = *(const float4*)(x + (long)s * INC + l8 * 4);
        acc.x = fmaf(v.x, ds, acc.x); acc.y = fmaf(v.y, ds, acc.y);
        acc.z = fmaf(v.z, ds, acc.z); acc.w = fmaf(v.w, ds, acc.w);
    }
    const float4 xv = *(const float4*)(x + (long)n * INC + l8 * 4);
    float4 r;
    r.x = (fmaf(xv.x, dn, acc.x)) * dn;
    r.y = (fmaf(xv.y, dn, acc.y)) * dn;
    r.z = (fmaf(xv.z, dn, acc.z)) * dn;
    r.w = (fmaf(xv.w, dn, acc.w)) * dn;
    *(float4*)(out + (long)n * INC + l8 * 4) = r;
}

// ------------------------------------------------------------------
// 64-ch fp16-payload gather (quarter-warp/node, uint4 = 8 halves, unroll 8):
// out = dinv[n]*(sum P[s] + P[n]) + b     (fp32 accumulate)
// ------------------------------------------------------------------
__global__ void __launch_bounds__(256)
k_gather64h(const __half* __restrict__ Ph, const float* __restrict__ b,
            float* __restrict__ out) {
    const int wid = threadIdx.x >> 5;
    const int lane = threadIdx.x & 31;
    const int q = lane >> 3;
    const int l8 = lane & 7;
    const int n = blockIdx.x * 32 + wid * 4 + q;
    if (n >= NN) return;
    const int o = __ldg(&g_off[n]);
    const int d = __ldg(&g_degi[n]);

    float acc[8];
    {
        uint4 u = *(const uint4*)(Ph + (long)n * HC + l8 * 8);
        const __half2* h = (const __half2*)&u;
#pragma unroll
        for (int m = 0; m < 4; m++) {
            float2 f = __half22float2(h[m]);
            acc[2 * m] = f.x; acc[2 * m + 1] = f.y;
        }
    }
    int i = 0;
    for (; i + 8 <= d; i += 8) {
        int s[8]; uint4 u[8];
#pragma unroll
        for (int m = 0; m < 8; m++) s[m] = __ldg(&g_csr[o + i + m]);
#pragma unroll
        for (int m = 0; m < 8; m++) u[m] = *(const uint4*)(Ph + (long)s[m] * HC + l8 * 8);
#pragma unroll
        for (int m = 0; m < 8; m++) {
            const __half2* h = (const __half2*)&u[m];
#pragma unroll
            for (int t = 0; t < 4; t++) {
                float2 f = __half22float2(h[t]);
                acc[2 * t] += f.x; acc[2 * t + 1] += f.y;
            }
        }
    }
    for (; i + 4 <= d; i += 4) {
        int s[4]; uint4 u[4];
#pragma unroll
        for (int m = 0; m < 4; m++) s[m] = __ldg(&g_csr[o + i + m]);
#pragma unroll
        for (int m = 0; m < 4; m++) u[m] = *(const uint4*)(Ph + (long)s[m] * HC + l8 * 8);
#pragma unroll
        for (int m = 0; m < 4; m++) {
            const __half2* h = (const __half2*)&u[m];
#pragma unroll
            for (int t = 0; t < 4; t++) {
                float2 f = __half22float2(h[t]);
                acc[2 * t] += f.x; acc[2 * t + 1] += f.y;
            }
        }
    }
    for (; i < d; i++) {
        const int s = __ldg(&g_csr[o + i]);
        const uint4 u = *(const uint4*)(Ph + (long)s * HC + l8 * 8);
        const __half2* h = (const __half2*)&u;
#pragma unroll
        for (int t = 0; t < 4; t++) {
            float2 f = __half22float2(h[t]);
            acc[2 * t] += f.x; acc[2 * t + 1] += f.y;
        }
    }
    const float dn = __ldg(&g_dinv[n]);
    const float4 bA = *(const float4*)(b + l8 * 8);
    const float4 bB = *(const float4*)(b + l8 * 8 + 4);
    float4 rA, rB;
    rA.x = fmaf(acc[0], dn, bA.x); rA.y = fmaf(acc[1], dn, bA.y);
    rA.z = fmaf(acc[2], dn, bA.z); rA.w = fmaf(acc[3], dn, bA.w);
    rB.x = fmaf(acc[4], dn, bB.x); rB.y = fmaf(acc[5], dn, bB.y);
    rB.z = fmaf(acc[6], dn, bB.z); rB.w = fmaf(acc[7], dn, bB.w);
    float* op = out + (long)n * HC + l8 * 8;
    *(float4*)(op) = rA; *(float4*)(op + 4) = rB;
}

// dec0 gather via graph table (half-warp/node, smem table, unroll 4)
__global__ void __launch_bounds__(256)
k_gather_tab(const int* __restrict__ batch, const float* __restrict__ b,
             float* __restrict__ out) {
    __shared__ float XWs[GG * HC];      // 16KB
    const int tid = threadIdx.x;
    {
        const float4* s4 = (const float4*)g_XW;
        float4* d4 = (float4*)XWs;
        for (int i = tid; i < GG * HC / 4; i += 256) d4[i] = s4[i];
    }
    __syncthreads();

    const int wid = tid >> 5;
    const int lane = tid & 31;
    const int h = lane >> 4;
    const int l16 = lane & 15;
    const int n = blockIdx.x * 16 + wid * 2 + h;
    if (n >= NN) return;
    const int o = __ldg(&g_off[n]);
    const int d = __ldg(&g_degi[n]);
    const float dn = __ldg(&g_dinv[n]);

    const int gn = __ldg(&batch[n]);
    float4 acc = *(const float4*)(XWs + gn * HC + l16 * 4);
    acc.x *= dn; acc.y *= dn; acc.z *= dn; acc.w *= dn;

    int i = 0;
    for (; i + 4 <= d; i += 4) {
        int s[4]; int g[4]; float ds[4];
#pragma unroll
        for (int m = 0; m < 4; m++) s[m] = __ldg(&g_csr[o + i + m]);
#pragma unroll
        for (int m = 0; m < 4; m++) g[m] = __ldg(&batch[s[m]]);
#pragma unroll
        for (int m = 0; m < 4; m++) ds[m] = __ldg(&g_dinv[s[m]]);
#pragma unroll
        for (int m = 0; m < 4; m++) {
            const float4 v = *(const float4*)(XWs + g[m] * HC + l16 * 4);
            acc.x = fmaf(v.x, ds[m], acc.x);
            acc.y = fmaf(v.y, ds[m], acc.y);
            acc.z = fmaf(v.z, ds[m], acc.z);
            acc.w = fmaf(v.w, ds[m], acc.w);
        }
    }
    for (; i < d; i++) {
        const int s = __ldg(&g_csr[o + i]);
        const int g = __ldg(&batch[s]);
        const float ds = __ldg(&g_dinv[s]);
        const float4 v = *(const float4*)(XWs + g * HC + l16 * 4);
        acc.x = fmaf(v.x, ds, acc.x); acc.y = fmaf(v.y, ds, acc.y);
        acc.z = fmaf(v.z, ds, acc.z); acc.w = fmaf(v.w, ds, acc.w);
    }
    const float4 b4 = __ldg(&((const float4*)b)[l16]);
    float4 r;
    r.x = fmaf(acc.x, dn, b4.x); r.y = fmaf(acc.y, dn, b4.y);
    r.z = fmaf(acc.z, dn, b4.z); r.w = fmaf(acc.w, dn, b4.w);
    *(float4*)(out + (long)n * HC + l16 * 4) = r;
}

// 32-ch fp32 payload gather (quarter-warp/node, unroll 8)
__global__ void __launch_bounds__(256)
k_gather32p(const float* __restrict__ P, const float* __restrict__ b,
            float* __restrict__ out) {
    const int wid = threadIdx.x >> 5;
    const int lane = threadIdx.x & 31;
    const int q = lane >> 3;
    const int l8 = lane & 7;
    const int n = blockIdx.x * 32 + wid * 4 + q;
    if (n >= NN) return;
    const int o = __ldg(&g_off[n]);
    const int d = __ldg(&g_degi[n]);

    float4 acc = *(const float4*)(P + (long)n * INC + l8 * 4);  // self
    int i = 0;
    for (; i + 8 <= d; i += 8) {
        int s[8]; float4 v[8];
#pragma unroll
        for (int m = 0; m < 8; m++) s[m] = __ldg(&g_csr[o + i + m]);
#pragma unroll
        for (int m = 0; m < 8; m++) v[m] = *(const float4*)(P + (long)s[m] * INC + l8 * 4);
#pragma unroll
        for (int m = 0; m < 8; m++) {
            acc.x += v[m].x; acc.y += v[m].y; acc.z += v[m].z; acc.w += v[m].w;
        }
    }
    for (; i + 4 <= d; i += 4) {
        int s[4]; float4 v[4];
#pragma unroll
        for (int m = 0; m < 4; m++) s[m] = __ldg(&g_csr[o + i + m]);
#pragma unroll
        for (int m = 0; m < 4; m++) v[m] = *(const float4*)(P + (long)s[m] * INC + l8 * 4);
#pragma unroll
        for (int m = 0; m < 4; m++) {
            acc.x += v[m].x; acc.y += v[m].y; acc.z += v[m].z; acc.w += v[m].w;
        }
    }
    for (; i < d; i++) {
        const int s = __ldg(&g_csr[o + i]);
        const float4 v = *(const float4*)(P + (long)s * INC + l8 * 4);
        acc.x += v.x; acc.y += v.y; acc.z += v.z; acc.w += v.w;
    }
    const float dn = __ldg(&g_dinv[n]);
    const float4 b4 = __ldg(&((const float4*)b)[l8]);
    float4 r;
    r.x = fmaf(acc.x, dn, b4.x); r.y = fmaf(acc.y, dn, b4.y);
    r.z = fmaf(acc.z, dn, b4.z); r.w = fmaf(acc.w, dn, b4.w);
    *(float4*)(out + (long)n * INC + l8 * 4) = r;
}

// ------------------------------------------------------------------
// GEMM: register-blocked 4 nodes x 8 channels per thread. blockDim=256.
// MODE 0: out = in@W + b                  (fp32)
// MODE 1: payload = (in@W)*dinv  fp32     (for fp32 gathers)
// MODE 2: payload = (in@W)*dinv  fp16     (packed half rows)
// ------------------------------------------------------------------
template <int KIN, int COUT, bool RELUIN, int MODE>
__global__ void __launch_bounds__(256, 3)
k_gemm(const float* __restrict__ in,
       const float* __restrict__ W,
       const float* __restrict__ b,
       float* __restrict__ dst) {
    constexpr int TPN = COUT / 8;
    constexpr int NG  = 256 / TPN;
    constexpr int NPB = NG * 4;
    constexpr int XSS = KIN + 1;

    __shared__ float Ws[KIN * COUT];
    __shared__ float bs[COUT];
    __shared__ float xs[NPB * XSS];

    const int tid = threadIdx.x;
    const int n0 = blockIdx.x * NPB;

    {
        const float4* W4 = (const float4*)W;
        float4* Ws4 = (float4*)Ws;
#pragma unroll
        for (int i = tid; i < KIN * COUT / 4; i += 256) Ws4[i] = W4[i];
    }
    if (tid < COUT) bs[tid] = (MODE == 0) ? b[tid] : 0.f;

    {
        constexpr int QPR = KIN / 4;
        constexpr int NQ = NPB * QPR;
        for (int i = tid; i < NQ; i += 256) {
            const int row = i / QPR;
            const int qc = i % QPR;
            float4 v = make_float4(0.f, 0.f, 0.f, 0.f);
            if (n0 + row < NN) {
                v = *(const float4*)(in + (long)(n0 + row) * KIN + qc * 4);
                if (RELUIN) {
                    v.x = fmaxf(v.x, 0.f); v.y = fmaxf(v.y, 0.f);
                    v.z = fmaxf(v.z, 0.f); v.w = fmaxf(v.w, 0.f);
                }
            }
            float* p = xs + row * XSS + qc * 4;
            p[0] = v.x; p[1] = v.y; p[2] = v.z; p[3] = v.w;
        }
    }
    __syncthreads();

    const int tc = tid % TPN;
    const int ng = tid / TPN;
    const int c0 = tc * 8;
    const int nb = ng * 4;

    float acc[4][8];
#pragma unroll
    for (int j = 0; j < 4; j++)
#pragma unroll
        for (int m = 0; m < 8; m++) acc[j][m] = 0.f;

    const float4* Ws4 = (const float4*)Ws;
#pragma unroll 8
    for (int k = 0; k < KIN; k++) {
        const float4 w0 = Ws4[(k * COUT + c0) >> 2];
        const float4 w1 = Ws4[((k * COUT + c0) >> 2) + 1];
        float xv[4];
#pragma unroll
        for (int j = 0; j < 4; j++) xv[j] = xs[(nb + j) * XSS + k];
#pragma unroll
        for (int j = 0; j < 4; j++) {
            acc[j][0] = fmaf(xv[j], w0.x, acc[j][0]);
            acc[j][1] = fmaf(xv[j], w0.y, acc[j][1]);
            acc[j][2] = fmaf(xv[j], w0.z, acc[j][2]);
            acc[j][3] = fmaf(xv[j], w0.w, acc[j][3]);
            acc[j][4] = fmaf(xv[j], w1.x, acc[j][4]);
            acc[j][5] = fmaf(xv[j], w1.y, acc[j][5]);
            acc[j][6] = fmaf(xv[j], w1.z, acc[j][6]);
            acc[j][7] = fmaf(xv[j], w1.w, acc[j][7]);
        }
    }

#pragma unroll
    for (int j = 0; j < 4; j++) {
        const int n = n0 + nb + j;
        if (n >= NN) break;
        if (MODE == 2) {
            const float d = g_dinv[n];
            union { uint4 u; __half2 h[4]; } pk;
            pk.h[0] = __floats2half2_rn(acc[j][0] * d, acc[j][1] * d);
            pk.h[1] = __floats2half2_rn(acc[j][2] * d, acc[j][3] * d);
            pk.h[2] = __floats2half2_rn(acc[j][4] * d, acc[j][5] * d);
            pk.h[3] = __floats2half2_rn(acc[j][6] * d, acc[j][7] * d);
            *(uint4*)((__half*)dst + (long)n * COUT + c0) = pk.u;
        } else if (MODE == 1) {
            const float d = g_dinv[n];
            float4 o0, o1;
            o0.x = acc[j][0] * d; o0.y = acc[j][1] * d;
            o0.z = acc[j][2] * d; o0.w = acc[j][3] * d;
            o1.x = acc[j][4] * d; o1.y = acc[j][5] * d;
            o1.z = acc[j][6] * d; o1.w = acc[j][7] * d;
            float* op = dst + (long)n * COUT + c0;
            *(float4*)(op) = o0; *(float4*)(op + 4) = o1;
        } else {
            float4 o0, o1;
            o0.x = acc[j][0] + bs[c0 + 0]; o0.y = acc[j][1] + bs[c0 + 1];
            o0.z = acc[j][2] + bs[c0 + 2]; o0.w = acc[j][3] + bs[c0 + 3];
            o1.x = acc[j][4] + bs[c0 + 4]; o1.y = acc[j][5] + bs[c0 + 5];
            o1.z = acc[j][6] + bs[c0 + 6]; o1.w = acc[j][7] + bs[c0 + 7];
            float* op = dst + (long)n * COUT + c0;
            *(float4*)(op) = o0; *(float4*)(op + 4) = o1;
        }
    }
}

// ------------------------------------------------------------------
// Pool: register run-length accumulation over sorted batch ids.
// ------------------------------------------------------------------
__global__ void k_pool(const int* __restrict__ batch, const float* __restrict__ h) {
    const int tid = threadIdx.x;
    const int c = tid % HC;
    const int r = tid / HC;
    float acc = 0.f;
    float cacc = 0.f;
    int curg = -1;
    for (int n = blockIdx.x * 4 + r; n < NN; n += gridDim.x * 4) {
        const int g = __ldg(&batch[n]);
        if (g != curg) {
            if (curg >= 0) {
                atomicAdd(&g_sums[curg * HC + c], acc);
                if (c == 0) atomicAdd(&g_cnt[curg], cacc);
            }
            acc = 0.f; cacc = 0.f; curg = g;
        }
        acc += fmaxf(h[(long)n * HC + c], 0.f);
        cacc += 1.f;
    }
    if (curg >= 0) {
        atomicAdd(&g_sums[curg * HC + c], acc);
        if (c == 0) atomicAdd(&g_cnt[curg], cacc);
    }
}

// ------------------------------------------------------------------
// Fused latent path: z = (sums/cnt)@Wp + bp  (also to d_out);
// D = relu(z@Wdp + bdp); XW = D @ W_dec0.   One block of 1024.
// ------------------------------------------------------------------
__global__ void __launch_bounds__(1024)
k_latent(const float* __restrict__ Wp, const float* __restrict__ bp,
         const float* __restrict__ Wdp, const float* __restrict__ bdp,
         const float* __restrict__ Wd0, float* __restrict__ zout) {
    __shared__ float zs[GG * LC];
    __shared__ float Ds[GG * HC];
    __shared__ float Wd0s[HC * HC];
    const int tid = threadIdx.x;        // 0..1023 = GG*LC exactly

    {
        const int g = tid / LC, l = tid % LC;
        const float inv = 1.0f / fmaxf(g_cnt[g], 1.0f);
        float s = bp[l];
#pragma unroll
        for (int k = 0; k < HC; k++)
            s = fmaf(g_sums[g * HC + k] * inv, Wp[k * LC + l], s);
        zs[g * LC + l] = s;
        zout[g * LC + l] = s;
    }
    for (int i = tid; i < HC * HC; i += 1024) Wd0s[i] = Wd0[i];
    __syncthreads();

    for (int i = tid; i < GG * HC; i += 1024) {
        const int g = i / HC, c = i % HC;
        float s = bdp[c];
#pragma unroll
        for (int k = 0; k < LC; k++) s = fmaf(zs[g * LC + k], Wdp[k * HC + c], s);
        Ds[i] = fmaxf(s, 0.f);
    }
    __syncthreads();

    for (int i = tid; i < GG * HC; i += 1024) {
        const int g = i / HC, c = i % HC;
        float s = 0.f;
#pragma unroll 16
        for (int k = 0; k < HC; k++) s = fmaf(Ds[g * HC + k], Wd0s[k * HC + c], s);
        g_XW[i] = s;
    }
}

// ------------------------------------------------------------------
extern "C" void kernel_launch(void* const* d_in, const int* in_sizes, int n_in,
                              void* d_out, int out_size) {
    const float* x       = (const float*)d_in[0];
    const int*   ei      = (const int*)  d_in[1];
    const int*   batch   = (const int*)  d_in[2];
    const float* W_enc0  = (const float*)d_in[3];
    const float* b_enc0  = (const float*)d_in[4];
    const float* W_enc1  = (const float*)d_in[5];
    const float* b_enc1  = (const float*)d_in[6];
    const float* W_enc2  = (const float*)d_in[7];
    const float* b_enc2  = (const float*)d_in[8];
    const float* W_proj  = (const float*)d_in[9];
    const float* b_proj  = (const float*)d_in[10];
    const float* W_decp  = (const float*)d_in[11];
    const float* b_decp  = (const float*)d_in[12];
    const float* W_dec0  = (const float*)d_in[13];
    const float* b_dec0  = (const float*)d_in[14];
    const float* W_dec1  = (const float*)d_in[15];
    const float* b_dec1  = (const float*)d_in[16];

    float* out  = (float*)d_out;
    float* xrec = out;             // [NN, INC]
    float* zout = out + NN * INC;  // [GG, LC]

    float *p_xws, *p_buf0, *p_buf1;
    cudaGetSymbolAddress((void**)&p_xws,  g_xws);
    cudaGetSymbolAddress((void**)&p_buf0, g_buf0);
    cudaGetSymbolAddress((void**)&p_buf1, g_buf1);

    const int TB = 256;
    const int gN    = (NN + TB - 1) / TB;
    const int gE    = (EE + TB - 1) / TB;
    const int gA64  = (NN + 127) / 128;     // GEMM COUT=64
    const int gA32  = (NN + 255) / 256;     // GEMM COUT=32
    const int gG64  = (NN + 15) / 16;       // gather_tab: 16 nodes/block
    const int gG32  = (NN + 31) / 32;       // quarter-warp gathers: 32 nodes/block

    // ---- degree, CSR build, dinv ----
    k_init<<<gN, TB>>>();
    k_count<<<gE, TB>>>(ei);
    k_scan1<<<NB1, 1024>>>();
    k_scan3<<<NB1, 1024>>>();
    k_fill<<<gE, TB>>>(ei);

    // ---- conv0 (fused aggregate in input space, then GEMM) ----
    k_gather32x<<<gG32, TB>>>(x, p_buf1);
    k_gemm<INC, HC, false, 0><<<gA64, TB>>>(p_buf1, W_enc0, b_enc0, p_buf0);

    // ---- conv1 (fp16 payload) ----
    k_gemm<HC, HC, true, 2><<<gA64, TB>>>(p_buf0, W_enc1, nullptr, p_xws);
    k_gather64h<<<gG32, TB>>>((const __half*)p_xws, b_enc1, p_buf1);
    // ---- conv2 (fp16 payload) ----
    k_gemm<HC, HC, true, 2><<<gA64, TB>>>(p_buf1, W_enc2, nullptr, p_xws);
    k_gather64h<<<gG32, TB>>>((const __half*)p_xws, b_enc2, p_buf0);

    // ---- pool + fused latent/decoder head ----
    k_pool<<<592, TB>>>(batch, p_buf0);
    k_latent<<<1, 1024>>>(W_proj, b_proj, W_decp, b_decp, W_dec0, zout);

    // ---- dec conv0 via graph table (gather, no N-wide GEMM) ----
    k_gather_tab<<<gG64, TB>>>(batch, b_dec0, p_buf1);

    // ---- dec conv1 (fp32 payload for output accuracy) ----
    k_gemm<HC, INC, true, 1><<<gA32, TB>>>(p_buf1, W_dec1, nullptr, p_xws);
    k_gather32p<<<gG32, TB>>>(p_xws, b_dec1, xrec);
}